// round 4
// baseline (speedup 1.0000x reference)
#include <cuda_runtime.h>
#include <cuda_bf16.h>
#include <cooperative_groups.h>

namespace cg = cooperative_groups;

#define RB      4
#define BINS    64      // RB^3
#define BATCH   64
#define CLS     40
#define THREADS 1024
#define NWARP   (THREADS / 32)

// Min/max over a 4-point triple (a,b,c as float4s):
//   a = (x0,y0,z0,x1)  b = (y1,z1,x2,y2)  c = (z2,x3,y3,z3)
#define MINMAX_TRIPLE(a, b, c)                                              \
    do {                                                                    \
        mn0 = fminf(mn0, fminf(fminf((a).x, (a).w), fminf((b).z, (c).y)));  \
        mx0 = fmaxf(mx0, fmaxf(fmaxf((a).x, (a).w), fmaxf((b).z, (c).y)));  \
        mn1 = fminf(mn1, fminf(fminf((a).y, (b).x), fminf((b).w, (c).z)));  \
        mx1 = fmaxf(mx1, fmaxf(fmaxf((a).y, (b).x), fmaxf((b).w, (c).z)));  \
        mn2 = fminf(mn2, fminf(fminf((a).z, (b).y), fminf((c).x, (c).w)));  \
        mx2 = fmaxf(mx2, fmaxf(fmaxf((a).z, (b).y), fmaxf((c).x, (c).w)));  \
    } while (0)

__device__ __forceinline__ int bin3(float px, float py, float pz,
                                    float s0, float t0, float s1, float t1,
                                    float s2, float t2) {
    int i0 = __float2int_rd(fmaf(px, s0, t0));
    int i1 = __float2int_rd(fmaf(py, s1, t1));
    int i2 = __float2int_rd(fmaf(pz, s2, t2));
    i0 = min(RB - 1, max(0, i0));
    i1 = min(RB - 1, max(0, i1));
    i2 = min(RB - 1, max(0, i2));
    return (i0 << 4) | (i1 << 2) | i2;
}

#define HIST_TRIPLE(a, b, c)                                                \
    do {                                                                    \
        atomicAdd(&myh[bin3((a).x, (a).y, (a).z, s0, t0, s1, t1, s2, t2)], 1); \
        atomicAdd(&myh[bin3((a).w, (b).x, (b).y, s0, t0, s1, t1, s2, t2)], 1); \
        atomicAdd(&myh[bin3((b).z, (b).w, (c).x, s0, t0, s1, t1, s2, t2)], 1); \
        atomicAdd(&myh[bin3((c).y, (c).z, (c).w, s0, t0, s1, t1, s2, t2)], 1); \
    } while (0)

__global__ void __cluster_dims__(2, 1, 1) __launch_bounds__(THREADS, 1)
k_fused(const float* __restrict__ x, const float* __restrict__ W,
        const float* __restrict__ bias, float* __restrict__ out,
        int N, int nTrip, float invN)
{
    __shared__ float sWt[BINS * CLS];   // W transposed: sWt[k*CLS + c]
    __shared__ int   sh[NWARP * BINS];  // per-warp sub-histograms
    __shared__ float sred[NWARP][6];
    __shared__ float sblk[6];           // this CTA's mn0..2, mx0..2
    __shared__ float sfin[6];           // cluster-combined
    __shared__ int   hfin[BINS];
    __shared__ float sc[BINS];

    cg::cluster_group cluster = cg::this_cluster();
    const int rank = cluster.block_rank();   // 0 or 1
    const int bat  = blockIdx.y;
    const int tid  = threadIdx.x;
    const int lane = tid & 31, warp = tid >> 5;

    const float*  xb = x + (size_t)bat * 3u * (size_t)N;
    const float4* p  = (const float4*)xb;
    const int half = (nTrip + 1) >> 1;
    const int beg  = rank * half;
    const int end  = min(nTrip, beg + half);
    const int rem  = N - nTrip * 4;          // 0 for N=100000

    if (rank == 0) {
        for (int i = tid; i < CLS * BINS; i += THREADS) {
            int c = i >> 6, k = i & 63;
            sWt[k * CLS + c] = W[i];
        }
    }
    for (int i = tid; i < NWARP * BINS; i += THREADS) sh[i] = 0;

    // ---- Pass 1: min/max (unroll x2 for MLP) ----
    float mn0 =  3.402823466e38f, mn1 = mn0, mn2 = mn0;
    float mx0 = -3.402823466e38f, mx1 = mx0, mx2 = mx0;
    {
        int i = beg + tid;
        for (; i + THREADS < end; i += 2 * THREADS) {
            float4 a0 = p[3 * i + 0];
            float4 b0 = p[3 * i + 1];
            float4 c0 = p[3 * i + 2];
            int j = i + THREADS;
            float4 a1 = p[3 * j + 0];
            float4 b1 = p[3 * j + 1];
            float4 c1 = p[3 * j + 2];
            MINMAX_TRIPLE(a0, b0, c0);
            MINMAX_TRIPLE(a1, b1, c1);
        }
        for (; i < end; i += THREADS) {
            float4 a = p[3 * i + 0];
            float4 b = p[3 * i + 1];
            float4 c = p[3 * i + 2];
            MINMAX_TRIPLE(a, b, c);
        }
    }
    if (rank == 0 && tid < rem) {
        int j = nTrip * 4 + tid;
        float vx = xb[3 * j + 0], vy = xb[3 * j + 1], vz = xb[3 * j + 2];
        mn0 = fminf(mn0, vx); mx0 = fmaxf(mx0, vx);
        mn1 = fminf(mn1, vy); mx1 = fmaxf(mx1, vy);
        mn2 = fminf(mn2, vz); mx2 = fmaxf(mx2, vz);
    }
    #pragma unroll
    for (int off = 16; off > 0; off >>= 1) {
        mn0 = fminf(mn0, __shfl_xor_sync(0xffffffffu, mn0, off));
        mn1 = fminf(mn1, __shfl_xor_sync(0xffffffffu, mn1, off));
        mn2 = fminf(mn2, __shfl_xor_sync(0xffffffffu, mn2, off));
        mx0 = fmaxf(mx0, __shfl_xor_sync(0xffffffffu, mx0, off));
        mx1 = fmaxf(mx1, __shfl_xor_sync(0xffffffffu, mx1, off));
        mx2 = fmaxf(mx2, __shfl_xor_sync(0xffffffffu, mx2, off));
    }
    if (lane == 0) {
        sred[warp][0] = mn0; sred[warp][1] = mn1; sred[warp][2] = mn2;
        sred[warp][3] = mx0; sred[warp][4] = mx1; sred[warp][5] = mx2;
    }
    __syncthreads();
    if (warp == 0) {   // NWARP == 32: lane l reduces warp l
        float v0 = sred[lane][0], v1 = sred[lane][1], v2 = sred[lane][2];
        float v3 = sred[lane][3], v4 = sred[lane][4], v5 = sred[lane][5];
        #pragma unroll
        for (int off = 16; off > 0; off >>= 1) {
            v0 = fminf(v0, __shfl_xor_sync(0xffffffffu, v0, off));
            v1 = fminf(v1, __shfl_xor_sync(0xffffffffu, v1, off));
            v2 = fminf(v2, __shfl_xor_sync(0xffffffffu, v2, off));
            v3 = fmaxf(v3, __shfl_xor_sync(0xffffffffu, v3, off));
            v4 = fmaxf(v4, __shfl_xor_sync(0xffffffffu, v4, off));
            v5 = fmaxf(v5, __shfl_xor_sync(0xffffffffu, v5, off));
        }
        if (lane == 0) {
            sblk[0] = v0; sblk[1] = v1; sblk[2] = v2;
            sblk[3] = v3; sblk[4] = v4; sblk[5] = v5;
        }
    }

    // ---- Cluster exchange of min/max ----
    cluster.sync();
    if (tid < 3) {
        const float* peer = cluster.map_shared_rank(sblk, rank ^ 1);
        sfin[tid]     = fminf(sblk[tid],     peer[tid]);
        sfin[tid + 3] = fmaxf(sblk[tid + 3], peer[tid + 3]);
    }
    __syncthreads();
    const float fm0 = sfin[0], fm1 = sfin[1], fm2 = sfin[2];
    const float s0 = (float)RB / (sfin[3] - fm0);
    const float s1 = (float)RB / (sfin[4] - fm1);
    const float s2 = (float)RB / (sfin[5] - fm2);
    const float t0 = -fm0 * s0, t1 = -fm1 * s1, t2 = -fm2 * s2;

    // ---- Pass 2: histogram (unroll x2) ----
    int* myh = &sh[warp << 6];
    {
        int i = beg + tid;
        for (; i + THREADS < end; i += 2 * THREADS) {
            float4 a0 = p[3 * i + 0];
            float4 b0 = p[3 * i + 1];
            float4 c0 = p[3 * i + 2];
            int j = i + THREADS;
            float4 a1 = p[3 * j + 0];
            float4 b1 = p[3 * j + 1];
            float4 c1 = p[3 * j + 2];
            HIST_TRIPLE(a0, b0, c0);
            HIST_TRIPLE(a1, b1, c1);
        }
        for (; i < end; i += THREADS) {
            float4 a = p[3 * i + 0];
            float4 b = p[3 * i + 1];
            float4 c = p[3 * i + 2];
            HIST_TRIPLE(a, b, c);
        }
    }
    if (rank == 0 && tid < rem) {
        int j = nTrip * 4 + tid;
        atomicAdd(&myh[bin3(xb[3 * j + 0], xb[3 * j + 1], xb[3 * j + 2],
                            s0, t0, s1, t1, s2, t2)], 1);
    }
    __syncthreads();

    if (tid < BINS) {
        int s = 0;
        #pragma unroll
        for (int w = 0; w < NWARP; w++) s += sh[(w << 6) + tid];
        hfin[tid] = s;
    }

    // ---- Cluster hist merge + epilogue (rank 0) ----
    cluster.sync();
    if (rank == 0 && tid < BINS) {
        const int* peer = cluster.map_shared_rank(hfin, 1);
        sc[tid] = (float)(hfin[tid] + peer[tid]) * invN;
    }
    cluster.sync();   // rank 1 must not exit before rank 0 read its smem

    if (rank == 0) {
        __syncthreads();
        if (tid < CLS) {
            float acc = bias[tid];
            #pragma unroll
            for (int k = 0; k < BINS; k++)
                acc = fmaf(sc[k], sWt[k * CLS + tid], acc);
            out[bat * CLS + tid] = acc;
        }
    }
}

extern "C" void kernel_launch(void* const* d_in, const int* in_sizes, int n_in,
                              void* d_out, int out_size) {
    const float* x = (const float*)d_in[0];
    const float* W = (const float*)d_in[1];
    const float* b = (const float*)d_in[2];
    float* out = (float*)d_out;

    int N = in_sizes[0] / (BATCH * 3);   // 100000
    int nTrip = N / 4;

    dim3 grid(2, BATCH);
    k_fused<<<grid, THREADS>>>(x, W, b, out, N, nTrip, 1.0f / (float)N);
}

// round 5
// speedup vs baseline: 1.0976x; 1.0976x over previous
#include <cuda_runtime.h>
#include <cuda_bf16.h>
#include <cooperative_groups.h>

namespace cg = cooperative_groups;

#define RB      4
#define BINS    64      // RB^3
#define BATCH   64
#define CLS     40
#define THREADS 1024
#define NWARP   (THREADS / 32)

__global__ void __cluster_dims__(2, 1, 1) __launch_bounds__(THREADS, 1)
k_fused(const float* __restrict__ x, const float* __restrict__ W,
        const float* __restrict__ bias, float* __restrict__ out,
        int N, int nTiles, int tailStart, float invN)
{
    __shared__ float sWt[BINS * CLS];   // W transposed: sWt[k*CLS + c]
    __shared__ int   sh[NWARP * BINS];  // per-warp sub-histograms
    __shared__ float sred[NWARP][6];
    __shared__ float sblk[6];           // this CTA's mn0..2, mx0..2
    __shared__ float sfin[6];           // cluster-combined
    __shared__ int   hfin[BINS];
    __shared__ float sc[BINS];

    cg::cluster_group cluster = cg::this_cluster();
    const int rank = cluster.block_rank();   // 0 or 1
    const int bat  = blockIdx.y;
    const int tid  = threadIdx.x;
    const int lane = tid & 31, warp = tid >> 5;
    const int gwarp = rank * NWARP + warp;   // 0..63 across cluster
    const int ctid  = rank * THREADS + tid;  // 0..2047 across cluster
    const int lr    = lane % 3;

    const float*  xb = x + (size_t)bat * 3u * (size_t)N;
    const float4* p4 = (const float4*)xb;

    if (rank == 0) {
        for (int i = tid; i < CLS * BINS; i += THREADS) {
            int c = i >> 6, k = i & 63;
            sWt[k * CLS + c] = W[i];
        }
    }
    for (int i = tid; i < NWARP * BINS; i += THREADS) sh[i] = 0;

    // ================= Pass 1: min/max, coalesced =================
    // Slot phases: V0 -> q=lr, V1 -> q=(lr+2)%3, V2 -> q=(lr+1)%3.
    // Per slot with phase q: (x,w)->comp q, y->comp q+1, z->comp q+2.
    const float FMAX =  3.402823466e38f;
    float mnA0 = FMAX, mnA1 = FMAX, mnA2 = FMAX;
    float mnB0 = FMAX, mnB1 = FMAX, mnB2 = FMAX;
    float mnC0 = FMAX, mnC1 = FMAX, mnC2 = FMAX;
    float mxA0 = -FMAX, mxA1 = -FMAX, mxA2 = -FMAX;
    float mxB0 = -FMAX, mxB1 = -FMAX, mxB2 = -FMAX;
    float mxC0 = -FMAX, mxC1 = -FMAX, mxC2 = -FMAX;

    for (int t = gwarp; t < nTiles; t += 2 * NWARP) {
        int b96 = t * 96;
        float4 A = p4[b96 + lane];
        float4 B = p4[b96 + 32 + lane];
        float4 C = p4[b96 + 64 + lane];
        float tn, tx;
        tn = fminf(A.x, A.w); tx = fmaxf(A.x, A.w);
        mnA0 = fminf(mnA0, tn);  mxA0 = fmaxf(mxA0, tx);
        mnA1 = fminf(mnA1, A.y); mxA1 = fmaxf(mxA1, A.y);
        mnA2 = fminf(mnA2, A.z); mxA2 = fmaxf(mxA2, A.z);
        tn = fminf(B.x, B.w); tx = fmaxf(B.x, B.w);
        mnB0 = fminf(mnB0, tn);  mxB0 = fmaxf(mxB0, tx);
        mnB1 = fminf(mnB1, B.y); mxB1 = fmaxf(mxB1, B.y);
        mnB2 = fminf(mnB2, B.z); mxB2 = fmaxf(mxB2, B.z);
        tn = fminf(C.x, C.w); tx = fmaxf(C.x, C.w);
        mnC0 = fminf(mnC0, tn);  mxC0 = fmaxf(mxC0, tx);
        mnC1 = fminf(mnC1, C.y); mxC1 = fmaxf(mxC1, C.y);
        mnC2 = fminf(mnC2, C.z); mxC2 = fmaxf(mxC2, C.z);
    }

    // Remap slot accumulators to absolute components.
    // G_d = combine(A_d, B_{d+1 mod 3 ...}) ; comp_c = G_{(c - lr) mod 3}
    float Gn0 = fminf(mnA0, fminf(mnB1, mnC2));
    float Gn1 = fminf(mnA1, fminf(mnB2, mnC0));
    float Gn2 = fminf(mnA2, fminf(mnB0, mnC1));
    float Gx0 = fmaxf(mxA0, fmaxf(mxB1, mxC2));
    float Gx1 = fmaxf(mxA1, fmaxf(mxB2, mxC0));
    float Gx2 = fmaxf(mxA2, fmaxf(mxB0, mxC1));
    float mn0 = (lr == 0) ? Gn0 : (lr == 1) ? Gn2 : Gn1;
    float mn1 = (lr == 0) ? Gn1 : (lr == 1) ? Gn0 : Gn2;
    float mn2 = (lr == 0) ? Gn2 : (lr == 1) ? Gn1 : Gn0;
    float mx0 = (lr == 0) ? Gx0 : (lr == 1) ? Gx2 : Gx1;
    float mx1 = (lr == 0) ? Gx1 : (lr == 1) ? Gx0 : Gx2;
    float mx2 = (lr == 0) ? Gx2 : (lr == 1) ? Gx1 : Gx0;

    // Tail points (not covered by tiles)
    for (int j = tailStart + ctid; j < N; j += 2 * THREADS) {
        float vx = xb[3 * j + 0], vy = xb[3 * j + 1], vz = xb[3 * j + 2];
        mn0 = fminf(mn0, vx); mx0 = fmaxf(mx0, vx);
        mn1 = fminf(mn1, vy); mx1 = fmaxf(mx1, vy);
        mn2 = fminf(mn2, vz); mx2 = fmaxf(mx2, vz);
    }

    #pragma unroll
    for (int off = 16; off > 0; off >>= 1) {
        mn0 = fminf(mn0, __shfl_xor_sync(0xffffffffu, mn0, off));
        mn1 = fminf(mn1, __shfl_xor_sync(0xffffffffu, mn1, off));
        mn2 = fminf(mn2, __shfl_xor_sync(0xffffffffu, mn2, off));
        mx0 = fmaxf(mx0, __shfl_xor_sync(0xffffffffu, mx0, off));
        mx1 = fmaxf(mx1, __shfl_xor_sync(0xffffffffu, mx1, off));
        mx2 = fmaxf(mx2, __shfl_xor_sync(0xffffffffu, mx2, off));
    }
    if (lane == 0) {
        sred[warp][0] = mn0; sred[warp][1] = mn1; sred[warp][2] = mn2;
        sred[warp][3] = mx0; sred[warp][4] = mx1; sred[warp][5] = mx2;
    }
    __syncthreads();
    if (warp == 0) {   // NWARP == 32
        float v0 = sred[lane][0], v1 = sred[lane][1], v2 = sred[lane][2];
        float v3 = sred[lane][3], v4 = sred[lane][4], v5 = sred[lane][5];
        #pragma unroll
        for (int off = 16; off > 0; off >>= 1) {
            v0 = fminf(v0, __shfl_xor_sync(0xffffffffu, v0, off));
            v1 = fminf(v1, __shfl_xor_sync(0xffffffffu, v1, off));
            v2 = fminf(v2, __shfl_xor_sync(0xffffffffu, v2, off));
            v3 = fmaxf(v3, __shfl_xor_sync(0xffffffffu, v3, off));
            v4 = fmaxf(v4, __shfl_xor_sync(0xffffffffu, v4, off));
            v5 = fmaxf(v5, __shfl_xor_sync(0xffffffffu, v5, off));
        }
        if (lane == 0) {
            sblk[0] = v0; sblk[1] = v1; sblk[2] = v2;
            sblk[3] = v3; sblk[4] = v4; sblk[5] = v5;
        }
    }

    // ---- Cluster exchange of min/max ----
    cluster.sync();
    if (tid < 3) {
        const float* peer = cluster.map_shared_rank(sblk, rank ^ 1);
        sfin[tid]     = fminf(sblk[tid],     peer[tid]);
        sfin[tid + 3] = fmaxf(sblk[tid + 3], peer[tid + 3]);
    }
    __syncthreads();
    const float fm0 = sfin[0], fm1 = sfin[1], fm2 = sfin[2];
    // Shrunken scale + bias: guarantees idx in [0, RB-1] with NO clamps.
    const float s0 = 3.99999f / (sfin[3] - fm0);
    const float s1 = 3.99999f / (sfin[4] - fm1);
    const float s2 = 3.99999f / (sfin[5] - fm2);
    const float t0 = 1e-6f - fm0 * s0;
    const float t1 = 1e-6f - fm1 * s1;
    const float t2 = 1e-6f - fm2 * s2;

    // ================= Pass 2: histogram, coalesced + shfl assembly =======
    int* myh = &sh[warp << 6];

    #define BIN3(px, py, pz)                                                 \
        do {                                                                 \
            int i0_ = __float2int_rd(fmaf((px), s0, t0));                    \
            int i1_ = __float2int_rd(fmaf((py), s1, t1));                    \
            int i2_ = __float2int_rd(fmaf((pz), s2, t2));                    \
            atomicAdd(&myh[i0_ * 16 + i1_ * 4 + i2_], 1);                    \
        } while (0)

    // Row m has start-offset sigma=m; per-lane o_m = (m - lr) mod 3.
    const int  o0 = (3 - lr) % 3, o1 = (4 - lr) % 3, o2 = (5 - lr) % 3;
    const bool e00 = (o0 == 0), e01 = (o0 == 1);
    const bool e10 = (o1 == 0), e11 = (o1 == 1);
    const bool e20 = (o2 == 0), e21 = (o2 == 1);
    const bool r0 = (lr == 0), r1 = (lr == 1);

    for (int t = gwarp; t < nTiles; t += 2 * NWARP) {
        int b96 = t * 96;
        float4 v0 = p4[b96 + lane];
        float4 v1 = p4[b96 + 32 + lane];
        float4 v2 = p4[b96 + 64 + lane];

        float nx0 = __shfl_down_sync(0xffffffffu, v0.x, 1);
        float ny0 = __shfl_down_sync(0xffffffffu, v0.y, 1);
        float nx1 = __shfl_down_sync(0xffffffffu, v1.x, 1);
        float ny1 = __shfl_down_sync(0xffffffffu, v1.y, 1);
        float nx2 = __shfl_down_sync(0xffffffffu, v2.x, 1);
        float ny2 = __shfl_down_sync(0xffffffffu, v2.y, 1);
        // lane 31: next floats come from lane 0 of the NEXT row
        float b1x = __shfl_sync(0xffffffffu, v1.x, 0);
        float b1y = __shfl_sync(0xffffffffu, v1.y, 0);
        float b2x = __shfl_sync(0xffffffffu, v2.x, 0);
        float b2y = __shfl_sync(0xffffffffu, v2.y, 0);
        if (lane == 31) { nx0 = b1x; ny0 = b1y; nx1 = b2x; ny1 = b2y; }

        // Row A-points: window f0..f4 = (v.x,v.y,v.z,v.w,nx)
        {
            float ax = e00 ? v0.x : e01 ? v0.y : v0.z;
            float ay = e00 ? v0.y : e01 ? v0.z : v0.w;
            float az = e00 ? v0.z : e01 ? v0.w : nx0;
            BIN3(ax, ay, az);
        }
        {
            float ax = e10 ? v1.x : e11 ? v1.y : v1.z;
            float ay = e10 ? v1.y : e11 ? v1.z : v1.w;
            float az = e10 ? v1.z : e11 ? v1.w : nx1;
            BIN3(ax, ay, az);
        }
        {
            float ax = e20 ? v2.x : e21 ? v2.y : v2.z;
            float ay = e20 ? v2.y : e21 ? v2.z : v2.w;
            float az = e20 ? v2.z : e21 ? v2.w : nx2;
            BIN3(ax, ay, az);
        }
        // B-point: the one row with o==0 (row index == lr): (f3,f4,f5)
        {
            float bx = r0 ? v0.w : r1 ? v1.w : v2.w;
            float by = r0 ? nx0  : r1 ? nx1  : nx2;
            float bz = r0 ? ny0  : r1 ? ny1  : ny2;
            BIN3(bx, by, bz);
        }
    }
    // Tail points
    for (int j = tailStart + ctid; j < N; j += 2 * THREADS) {
        BIN3(xb[3 * j + 0], xb[3 * j + 1], xb[3 * j + 2]);
    }
    __syncthreads();

    if (tid < BINS) {
        int s = 0;
        #pragma unroll
        for (int w = 0; w < NWARP; w++) s += sh[(w << 6) + tid];
        hfin[tid] = s;
    }

    // ---- Cluster hist merge + epilogue (rank 0) ----
    cluster.sync();
    if (rank == 0 && tid < BINS) {
        const int* peer = cluster.map_shared_rank(hfin, 1);
        sc[tid] = (float)(hfin[tid] + peer[tid]) * invN;
    }
    cluster.sync();   // rank 1 must not exit before rank 0 read its smem

    if (rank == 0) {
        __syncthreads();
        if (tid < CLS) {
            float acc = bias[tid];
            #pragma unroll
            for (int k = 0; k < BINS; k++)
                acc = fmaf(sc[k], sWt[k * CLS + tid], acc);
            out[bat * CLS + tid] = acc;
        }
    }
}

extern "C" void kernel_launch(void* const* d_in, const int* in_sizes, int n_in,
                              void* d_out, int out_size) {
    const float* x = (const float*)d_in[0];
    const float* W = (const float*)d_in[1];
    const float* b = (const float*)d_in[2];
    float* out = (float*)d_out;

    int N = in_sizes[0] / (BATCH * 3);   // 100000
    // Tiles of 96 float4s (= 128 points) require 3N % 4 == 0 for alignment.
    int nf4    = ((3 * N) % 4 == 0) ? (3 * N) / 4 : 0;
    int nTiles = nf4 / 96;
    int tailStart = nTiles * 128;        // first point not covered by tiles

    dim3 grid(2, BATCH);
    k_fused<<<grid, THREADS>>>(x, W, b, out, N, nTiles, tailStart,
                               1.0f / (float)N);
}